// round 2
// baseline (speedup 1.0000x reference)
#include <cuda_runtime.h>
#include <cstdint>

// ---------------------------------------------------------------------------
// SNN: x(32768,128) -> threefry/bernoulli encode (T=8) -> [Lin+LIF]x3 -> Lin -> mean_t
// Shapes: 128 -> 256 -> 128 -> 64 -> 64.  LIF: tau=2, v_th=1, hard reset to 0.
// ---------------------------------------------------------------------------

#define T_STEPS 8
#define B_TOTAL 32768

// Scratch (no cudaMalloc allowed)
__device__ uint32_t g_bits[1u << 20];          // packed input spikes: word = g_bits[(t<<17)+(b<<2)+wi]
__device__ float g_Wt1[128 * 256];             // W1^T  [i][o]
__device__ float g_Wt2[256 * 128];
__device__ float g_Wt3[128 * 64];
__device__ float g_Wt4[64 * 64];

// ---------------------------------------------------------------------------
// Weight transpose: torch layout W[o][i] -> Wt[i][o] so 8 consecutive outputs
// load as 2x float4.
// ---------------------------------------------------------------------------
__global__ void prep_kernel(const float* __restrict__ W1, const float* __restrict__ W2,
                            const float* __restrict__ W3, const float* __restrict__ W4)
{
    int i = blockIdx.x * blockDim.x + threadIdx.x;
    if (i < 256 * 128) { int o = i / 128, k = i % 128; g_Wt1[k * 256 + o] = W1[i]; }
    if (i < 128 * 256) { int o = i / 256, k = i % 256; g_Wt2[k * 128 + o] = W2[i]; }
    if (i < 64 * 128)  { int o = i / 128, k = i % 128; g_Wt3[k * 64 + o]  = W3[i]; }
    if (i < 64 * 64)   { int o = i / 64,  k = i % 64;  g_Wt4[k * 64 + o]  = W4[i]; }
}

// ---------------------------------------------------------------------------
// JAX threefry2x32, key = (0, 42)  [jax.random.key(42)]
// ---------------------------------------------------------------------------
__device__ __forceinline__ void threefry2x32_42(uint32_t& x0, uint32_t& x1)
{
    const uint32_t k0 = 0u, k1 = 42u, k2 = 0u ^ 42u ^ 0x1BD11BDAu;
    x0 += k0; x1 += k1;
#define TF_RND(r) { x0 += x1; x1 = (x1 << (r)) | (x1 >> (32 - (r))); x1 ^= x0; }
    TF_RND(13) TF_RND(15) TF_RND(26) TF_RND(6)   x0 += k1; x1 += k2 + 1u;
    TF_RND(17) TF_RND(29) TF_RND(16) TF_RND(24)  x0 += k2; x1 += k0 + 2u;
    TF_RND(13) TF_RND(15) TF_RND(26) TF_RND(6)   x0 += k0; x1 += k1 + 3u;
    TF_RND(17) TF_RND(29) TF_RND(16) TF_RND(24)  x0 += k1; x1 += k2 + 4u;
    TF_RND(13) TF_RND(15) TF_RND(26) TF_RND(6)   x0 += k2; x1 += k0 + 5u;
#undef TF_RND
}

// Encode: count = 2^25 bits.  JAX splits iota(2^25) in halves: element j of
// first half pairs with element j+2^24: threefry(key,(j, j+2^24)) -> (bits[j], bits[j+2^24]).
// idx = t*2^22 + b*128 + d, so low 22 bits of j directly index x[b*128+d].
__global__ void encode_kernel(const float* __restrict__ x)
{
    uint32_t j = blockIdx.x * 256u + threadIdx.x;          // [0, 2^24)
    uint32_t x0 = j, x1 = j + (1u << 24);
    threefry2x32_42(x0, x1);

    float xv = __ldg(&x[j & 0x3FFFFFu]);                   // x[b*128+d]
    float p  = 1.0f / (1.0f + expf(-xv));                  // sigmoid

    // uniform[0,1): bitcast((bits>>9)|0x3f800000) - 1 ;  spike = u < p
    float u0 = __uint_as_float((x0 >> 9) | 0x3f800000u) - 1.0f;
    float u1 = __uint_as_float((x1 >> 9) | 0x3f800000u) - 1.0f;
    unsigned m0 = __ballot_sync(0xFFFFFFFFu, u0 < p);
    unsigned m1 = __ballot_sync(0xFFFFFFFFu, u1 < p);
    if ((threadIdx.x & 31u) == 0) {
        g_bits[j >> 5] = m0;
        g_bits[(j >> 5) + (1u << 19)] = m1;
    }
}

// bit k of m -> 1.0f / 0.0f without I2F: arithmetic-shift the bit to a full
// mask, AND with the bit pattern of 1.0f.
__device__ __forceinline__ float bit_to_float(uint32_t m, int k)
{
    return __uint_as_float(((uint32_t)((int32_t)(m << (31 - k)) >> 31)) & 0x3f800000u);
}

// ---------------------------------------------------------------------------
// Fused network. Block = 128 threads = 64 batch elements x 2 halves.
// Each thread computes its half of each layer's outputs, all T steps, spikes
// bit-packed into smem.  Weights stream through L1 (16 lanes/address broadcast).
// ---------------------------------------------------------------------------

template <int NI, int NO>
__device__ __forceinline__ void lif_layer(const uint32_t* __restrict__ in_words, // [8][NI/32] this b
                                          uint32_t* __restrict__ out_words,      // [8][NO/32] this b
                                          const float* __restrict__ Wt,          // [NI][NO]
                                          const float* __restrict__ bias,
                                          int half)
{
    constexpr int NWI = NI / 32;
    constexpr int NWO = NO / 32;
    constexpr int WPH = NWO / 2;          // output words per half (>=1)

#pragma unroll 1
    for (int w = 0; w < WPH; ++w) {
        const int word_idx = half * WPH + w;
#pragma unroll 1
        for (int c4 = 0; c4 < 4; ++c4) {
            const int o0 = word_idx * 32 + c4 * 8;
            const float4 bA = __ldg((const float4*)(bias + o0));
            const float4 bB = __ldg((const float4*)(bias + o0 + 4));
            float v[8];
#pragma unroll
            for (int jj = 0; jj < 8; ++jj) v[jj] = 0.0f;

#pragma unroll 1
            for (int t = 0; t < 8; ++t) {
                float cur[8] = {bA.x, bA.y, bA.z, bA.w, bB.x, bB.y, bB.z, bB.w};
                const uint32_t* iw = in_words + t * NWI;
#pragma unroll 1
                for (int wi = 0; wi < NWI; ++wi) {
                    const uint32_t m = iw[wi];
                    const float* wbase = Wt + (wi * 32) * NO + o0;
#pragma unroll
                    for (int k = 0; k < 32; ++k) {
                        const float s = bit_to_float(m, k);
                        const float4 wA = __ldg((const float4*)(wbase + k * NO));
                        const float4 wB = __ldg((const float4*)(wbase + k * NO + 4));
                        cur[0] = fmaf(s, wA.x, cur[0]);
                        cur[1] = fmaf(s, wA.y, cur[1]);
                        cur[2] = fmaf(s, wA.z, cur[2]);
                        cur[3] = fmaf(s, wA.w, cur[3]);
                        cur[4] = fmaf(s, wB.x, cur[4]);
                        cur[5] = fmaf(s, wB.y, cur[5]);
                        cur[6] = fmaf(s, wB.z, cur[6]);
                        cur[7] = fmaf(s, wB.w, cur[7]);
                    }
                }
                uint32_t bits = 0;
#pragma unroll
                for (int jj = 0; jj < 8; ++jj) {
                    // v += (cur - v)/tau ; spike if v>=1 ; hard reset
                    float vn = fmaf(cur[jj] - v[jj], 0.5f, v[jj]);
                    bool sp = (vn >= 1.0f);
                    bits |= sp ? (1u << jj) : 0u;
                    v[jj] = sp ? 0.0f : vn;
                }
                ((uint8_t*)(out_words + t * NWO + word_idx))[c4] = (uint8_t)bits;
            }
        }
    }
}

__device__ __forceinline__ void out_layer(const uint32_t* __restrict__ in_words, // [8][2]
                                          const float* __restrict__ Wt4,         // [64][64]
                                          const float* __restrict__ b4,
                                          float* __restrict__ outp,              // &out[b*64]
                                          int half)
{
#pragma unroll 1
    for (int c = 0; c < 4; ++c) {
        const int o0 = half * 32 + c * 8;
        float acc[8];
#pragma unroll
        for (int jj = 0; jj < 8; ++jj) acc[jj] = 0.0f;

#pragma unroll 1
        for (int t = 0; t < 8; ++t) {
            const uint32_t* iw = in_words + t * 2;
#pragma unroll 1
            for (int wi = 0; wi < 2; ++wi) {
                const uint32_t m = iw[wi];
                const float* wbase = Wt4 + (wi * 32) * 64 + o0;
#pragma unroll
                for (int k = 0; k < 32; ++k) {
                    const float s = bit_to_float(m, k);
                    const float4 wA = __ldg((const float4*)(wbase + k * 64));
                    const float4 wB = __ldg((const float4*)(wbase + k * 64 + 4));
                    acc[0] = fmaf(s, wA.x, acc[0]);
                    acc[1] = fmaf(s, wA.y, acc[1]);
                    acc[2] = fmaf(s, wA.z, acc[2]);
                    acc[3] = fmaf(s, wA.w, acc[3]);
                    acc[4] = fmaf(s, wB.x, acc[4]);
                    acc[5] = fmaf(s, wB.y, acc[5]);
                    acc[6] = fmaf(s, wB.z, acc[6]);
                    acc[7] = fmaf(s, wB.w, acc[7]);
                }
            }
        }
        const float4 bA = __ldg((const float4*)(b4 + o0));
        const float4 bB = __ldg((const float4*)(b4 + o0 + 4));
        outp[o0 + 0] = acc[0] * 0.125f + bA.x;
        outp[o0 + 1] = acc[1] * 0.125f + bA.y;
        outp[o0 + 2] = acc[2] * 0.125f + bA.z;
        outp[o0 + 3] = acc[3] * 0.125f + bA.w;
        outp[o0 + 4] = acc[4] * 0.125f + bB.x;
        outp[o0 + 5] = acc[5] * 0.125f + bB.y;
        outp[o0 + 6] = acc[6] * 0.125f + bB.z;
        outp[o0 + 7] = acc[7] * 0.125f + bB.w;
    }
}

__global__ void __launch_bounds__(128) snn_kernel(const float* __restrict__ b1,
                                                  const float* __restrict__ b2,
                                                  const float* __restrict__ b3,
                                                  const float* __restrict__ b4,
                                                  float* __restrict__ out)
{
    __shared__ uint32_t s_in[64 * 8 * 4];   // input spikes  [bl][t][4]
    __shared__ uint32_t s_s1[64 * 8 * 8];   // layer1 spikes [bl][t][8]
    __shared__ uint32_t s_s2[64 * 8 * 4];   // layer2 spikes [bl][t][4]
    __shared__ uint32_t s_s3[64 * 8 * 2];   // layer3 spikes [bl][t][2]

    const int tid = threadIdx.x;
    const int b0 = blockIdx.x * 64;

    // stage input spike bits: global layout word(t,b,wi) = g_bits[(t<<17)+(b<<2)+wi]
    for (int idx = tid; idx < 64 * 8 * 4; idx += 128) {
        const int bl = idx >> 5;
        const int t  = (idx >> 2) & 7;
        const int wi = idx & 3;
        s_in[idx] = g_bits[(t << 17) + ((b0 + bl) << 2) + wi];
    }
    __syncthreads();

    const int bl = tid >> 1;
    const int half = tid & 1;

    lif_layer<128, 256>(s_in + bl * 32, s_s1 + bl * 64, g_Wt1, b1, half);
    __syncthreads();
    lif_layer<256, 128>(s_s1 + bl * 64, s_s2 + bl * 32, g_Wt2, b2, half);
    __syncthreads();
    lif_layer<128, 64>(s_s2 + bl * 32, s_s3 + bl * 16, g_Wt3, b3, half);
    __syncthreads();
    out_layer(s_s3 + bl * 16, g_Wt4, b4, out + (b0 + bl) * 64, half);
}

// ---------------------------------------------------------------------------
extern "C" void kernel_launch(void* const* d_in, const int* in_sizes, int n_in,
                              void* d_out, int out_size)
{
    const float* x  = (const float*)d_in[0];
    const float* W1 = (const float*)d_in[1];
    const float* b1 = (const float*)d_in[2];
    const float* W2 = (const float*)d_in[3];
    const float* b2 = (const float*)d_in[4];
    const float* W3 = (const float*)d_in[5];
    const float* b3 = (const float*)d_in[6];
    const float* W4 = (const float*)d_in[7];
    const float* b4 = (const float*)d_in[8];
    float* out = (float*)d_out;

    prep_kernel<<<128, 256>>>(W1, W2, W3, W4);
    encode_kernel<<<(1 << 24) / 256, 256>>>(x);
    snn_kernel<<<B_TOTAL / 64, 128>>>(b1, b2, b3, b4, out);
}

// round 7
// speedup vs baseline: 5.2953x; 5.2953x over previous
#include <cuda_runtime.h>
#include <cstdint>

// ---------------------------------------------------------------------------
// SNN: x(32768,128) -> threefry/bernoulli encode (T=8) -> [Lin+LIF]x3 -> Lin -> mean_t
// Shapes: 128 -> 256 -> 128 -> 64 -> 64.  LIF: tau=2, v_th=1, hard reset to 0.
//
// v3: one persistent 512-thread block per SM (grid=148). Weights staged into
// smem per layer; spikes bit-packed in smem, el-minor (bank-conflict free).
// Inner product uses packed fma.rn.f32x2 (FFMA2): pair = 2 adjacent outputs.
// ---------------------------------------------------------------------------

#define B_TOTAL 32768
#define NBLK 148
#define NTHR 512
#define NEL 256        // max batch elements per block (smem sizing)

// Scratch (no cudaMalloc allowed)
__device__ uint32_t g_bits[1u << 20];                 // word = g_bits[(t<<17)+(b<<2)+wi]
__device__ __align__(16) float g_Wt1[128 * 256];      // W^T [i][o]
__device__ __align__(16) float g_Wt2[256 * 128];
__device__ __align__(16) float g_Wt3[128 * 64];
__device__ __align__(16) float g_Wt4[64 * 64];

// smem layout (bytes)
#define SM_W   0                      // float[32768]  = 131072 B (layer weights)
#define SM_X   131072                 // u32[32*256]   =  32768 B (s_in / s2)
#define SM_Y   (131072 + 32768)       // u32[64*256]   =  65536 B (s1 / s3)
#define SM_B   (131072 + 32768 + 65536) // float[512]  =   2048 B (biases)
#define SM_TOTAL (131072 + 32768 + 65536 + 2048)      // 231424 <= 232448

// ---------------------------------------------------------------------------
__global__ void prep_kernel(const float* __restrict__ W1, const float* __restrict__ W2,
                            const float* __restrict__ W3, const float* __restrict__ W4)
{
    int i = blockIdx.x * blockDim.x + threadIdx.x;
    if (i < 256 * 128) { int o = i / 128, k = i % 128; g_Wt1[k * 256 + o] = W1[i]; }
    if (i < 128 * 256) { int o = i / 256, k = i % 256; g_Wt2[k * 128 + o] = W2[i]; }
    if (i < 64 * 128)  { int o = i / 128, k = i % 128; g_Wt3[k * 64 + o]  = W3[i]; }
    if (i < 64 * 64)   { int o = i / 64,  k = i % 64;  g_Wt4[k * 64 + o]  = W4[i]; }
}

// ---------------------------------------------------------------------------
// JAX threefry2x32, key = (0, 42)
// ---------------------------------------------------------------------------
__device__ __forceinline__ void threefry2x32_42(uint32_t& x0, uint32_t& x1)
{
    const uint32_t k0 = 0u, k1 = 42u, k2 = 0u ^ 42u ^ 0x1BD11BDAu;
    x0 += k0; x1 += k1;
#define TF_RND(r) { x0 += x1; x1 = (x1 << (r)) | (x1 >> (32 - (r))); x1 ^= x0; }
    TF_RND(13) TF_RND(15) TF_RND(26) TF_RND(6)   x0 += k1; x1 += k2 + 1u;
    TF_RND(17) TF_RND(29) TF_RND(16) TF_RND(24)  x0 += k2; x1 += k0 + 2u;
    TF_RND(13) TF_RND(15) TF_RND(26) TF_RND(6)   x0 += k0; x1 += k1 + 3u;
    TF_RND(17) TF_RND(29) TF_RND(16) TF_RND(24)  x0 += k1; x1 += k2 + 4u;
    TF_RND(13) TF_RND(15) TF_RND(26) TF_RND(6)   x0 += k2; x1 += k0 + 5u;
#undef TF_RND
}

__global__ void encode_kernel(const float* __restrict__ x)
{
    uint32_t j = blockIdx.x * 256u + threadIdx.x;          // [0, 2^24)
    uint32_t x0 = j, x1 = j + (1u << 24);
    threefry2x32_42(x0, x1);

    float xv = __ldg(&x[j & 0x3FFFFFu]);
    float p  = 1.0f / (1.0f + expf(-xv));

    float u0 = __uint_as_float((x0 >> 9) | 0x3f800000u) - 1.0f;
    float u1 = __uint_as_float((x1 >> 9) | 0x3f800000u) - 1.0f;
    unsigned m0 = __ballot_sync(0xFFFFFFFFu, u0 < p);
    unsigned m1 = __ballot_sync(0xFFFFFFFFu, u1 < p);
    if ((threadIdx.x & 31u) == 0) {
        g_bits[j >> 5] = m0;
        g_bits[(j >> 5) + (1u << 19)] = m1;
    }
}

// ---------------------------------------------------------------------------
typedef unsigned long long ull;

#define FFMA2(acc, a, b) asm("fma.rn.f32x2 %0, %1, %2, %0;" : "+l"(acc) : "l"(a), "l"(b))
#define ADD2(d, a, b)    asm("add.rn.f32x2 %0, %1, %2;" : "=l"(d) : "l"(a), "l"(b))

__device__ __forceinline__ ull dup2(uint32_t r)
{
    ull v; asm("mov.b64 %0, {%1, %1};" : "=l"(v) : "r"(r)); return v;
}
__device__ __forceinline__ void unpack2(ull v, float& lo, float& hi)
{
    asm("mov.b64 {%0, %1}, %2;" : "=f"(lo), "=f"(hi) : "l"(v));
}

__device__ __forceinline__ void stage_w(float* dst, const float* src, int n, int tid)
{
    const float4* s4 = (const float4*)src;
    float4* d4 = (float4*)dst;
    for (int i = tid; i < n / 4; i += NTHR) d4[i] = s4[i];
}

// ---------------------------------------------------------------------------
// One layer for one batch element (this thread handles `half` of NO outputs).
// sIn: [t][wi][NEL] packed bits, sOut likewise.  sW: [NI][NO] smem weights.
// Per group of 8 adjacent outputs: accumulate all 8 timesteps with FFMA2
// (pair = 2 outputs), then run the LIF scan and emit spike bits.
// ---------------------------------------------------------------------------
template <int NI, int NO, bool IS_OUT>
__device__ __forceinline__ void run_layer(const uint32_t* __restrict__ sIn,
                                          uint32_t* __restrict__ sOut,
                                          const float* __restrict__ sW,
                                          const float* __restrict__ sB,
                                          float* __restrict__ gOut,
                                          int el, int half)
{
    constexpr int NWI = NI / 32;
    constexpr int NWO = NO / 32;
    constexpr int NG  = NO / 16;        // groups of 8 outputs per half-thread

#pragma unroll 1
    for (int g = 0; g < NG; ++g) {
        const int o0 = half * (NO / 2) + g * 8;

        ull acc[8][4];
        if (!IS_OUT) {
            const ull* bp = (const ull*)(sB + o0);
            ull b0 = bp[0], b1 = bp[1], b2 = bp[2], b3 = bp[3];
#pragma unroll
            for (int t = 0; t < 8; ++t) { acc[t][0] = b0; acc[t][1] = b1; acc[t][2] = b2; acc[t][3] = b3; }
        } else {
#pragma unroll
            for (int t = 0; t < 8; ++t) { acc[t][0] = 0; acc[t][1] = 0; acc[t][2] = 0; acc[t][3] = 0; }
        }

#pragma unroll 1
        for (int wi = 0; wi < NWI; ++wi) {
            uint32_t ms[8];
#pragma unroll
            for (int t = 0; t < 8; ++t) ms[t] = sIn[(t * NWI + wi) * NEL + el];

            const float* wrow = sW + (wi * 32) * NO + o0;
#pragma unroll 8
            for (int kk = 0; kk < 32; ++kk) {
                const int k = 31 - kk;                     // bit 31 first (MSB via sign)
                const ulonglong2 wa = *(const ulonglong2*)(wrow + k * NO);
                const ulonglong2 wb = *(const ulonglong2*)(wrow + k * NO + 4);
#pragma unroll
                for (int t = 0; t < 8; ++t) {
                    uint32_t sm = ((uint32_t)((int32_t)ms[t] >> 31)) & 0x3f800000u;
                    ms[t] <<= 1;
                    ull s2 = dup2(sm);
                    FFMA2(acc[t][0], s2, wa.x);
                    FFMA2(acc[t][1], s2, wa.y);
                    FFMA2(acc[t][2], s2, wb.x);
                    FFMA2(acc[t][3], s2, wb.y);
                }
            }
        }

        if (!IS_OUT) {
            // LIF scan over t for these 8 outputs
            float v[8];
#pragma unroll
            for (int o = 0; o < 8; ++o) v[o] = 0.0f;
            const int widx = o0 >> 5;
            const int byi  = (o0 >> 3) & 3;
#pragma unroll
            for (int t = 0; t < 8; ++t) {
                float c[8];
                unpack2(acc[t][0], c[0], c[1]);
                unpack2(acc[t][1], c[2], c[3]);
                unpack2(acc[t][2], c[4], c[5]);
                unpack2(acc[t][3], c[6], c[7]);
                uint32_t bits = 0;
#pragma unroll
                for (int o = 0; o < 8; ++o) {
                    float vn = fmaf(c[o] - v[o], 0.5f, v[o]);   // v + (x-v)/2
                    bool sp = (vn >= 1.0f);
                    bits |= sp ? (1u << o) : 0u;
                    v[o] = sp ? 0.0f : vn;
                }
                ((uint8_t*)&sOut[(t * NWO + widx) * NEL + el])[byi] = (uint8_t)bits;
            }
        } else {
            // sum over t, /8, + bias, store
#pragma unroll
            for (int p = 0; p < 4; ++p) {
                ull s = acc[0][p];
#pragma unroll
                for (int t = 1; t < 8; ++t) ADD2(s, s, acc[t][p]);
                float lo, hi;
                unpack2(s, lo, hi);
                gOut[o0 + 2 * p]     = fmaf(lo, 0.125f, sB[o0 + 2 * p]);
                gOut[o0 + 2 * p + 1] = fmaf(hi, 0.125f, sB[o0 + 2 * p + 1]);
            }
        }
    }
}

// ---------------------------------------------------------------------------
__global__ void __launch_bounds__(NTHR, 1) snn_kernel(const float* __restrict__ b1,
                                                      const float* __restrict__ b2,
                                                      const float* __restrict__ b3,
                                                      const float* __restrict__ b4,
                                                      float* __restrict__ out)
{
    extern __shared__ char smem[];
    float*    sW = (float*)(smem + SM_W);
    uint32_t* X  = (uint32_t*)(smem + SM_X);
    uint32_t* Y  = (uint32_t*)(smem + SM_Y);
    float*    sB = (float*)(smem + SM_B);

    const int tid = threadIdx.x;
    const int bid = blockIdx.x;
    const int b_start = (bid * B_TOTAL) / NBLK;
    const int b_end   = ((bid + 1) * B_TOTAL) / NBLK;
    const int n_el    = b_end - b_start;

    // biases -> smem: [0:256) b1, [256:384) b2, [384:448) b3, [448:512) b4
    if (tid < 256)      sB[tid] = b1[tid];
    else if (tid < 384) sB[tid] = b2[tid - 256];
    else if (tid < 448) sB[tid] = b3[tid - 384];
    else                sB[tid] = b4[tid - 448];

    // input spikes -> X, el-minor: X[(t*4+wi)*256 + el]
    for (int idx = tid; idx < 8 * 4 * NEL; idx += NTHR) {
        const int el  = idx & 255;
        const int twi = idx >> 8;
        const int t   = twi >> 2;
        const int wi  = twi & 3;
        const int b   = b_start + el;
        X[idx] = (el < n_el) ? g_bits[(t << 17) + (b << 2) + wi] : 0u;
    }
    stage_w(sW, g_Wt1, 128 * 256, tid);
    __syncthreads();

    const int el = tid >> 1;
    const int half = tid & 1;
    const bool act = el < n_el;

    if (act) run_layer<128, 256, false>(X, Y, sW, sB, nullptr, el, half);
    __syncthreads();
    stage_w(sW, g_Wt2, 256 * 128, tid);
    __syncthreads();

    if (act) run_layer<256, 128, false>(Y, X, sW, sB + 256, nullptr, el, half);
    __syncthreads();
    stage_w(sW, g_Wt3, 128 * 64, tid);
    __syncthreads();

    if (act) run_layer<128, 64, false>(X, Y, sW, sB + 384, nullptr, el, half);
    __syncthreads();
    stage_w(sW, g_Wt4, 64 * 64, tid);
    __syncthreads();

    if (act) run_layer<64, 64, true>(Y, nullptr, sW, sB + 448,
                                     out + (b_start + el) * 64, el, half);
}

// ---------------------------------------------------------------------------
extern "C" void kernel_launch(void* const* d_in, const int* in_sizes, int n_in,
                              void* d_out, int out_size)
{
    const float* x  = (const float*)d_in[0];
    const float* W1 = (const float*)d_in[1];
    const float* b1 = (const float*)d_in[2];
    const float* W2 = (const float*)d_in[3];
    const float* b2 = (const float*)d_in[4];
    const float* W3 = (const float*)d_in[5];
    const float* b3 = (const float*)d_in[6];
    const float* W4 = (const float*)d_in[7];
    const float* b4 = (const float*)d_in[8];
    float* out = (float*)d_out;

    cudaFuncSetAttribute(snn_kernel, cudaFuncAttributeMaxDynamicSharedMemorySize, SM_TOTAL);

    prep_kernel<<<128, 256>>>(W1, W2, W3, W4);
    encode_kernel<<<(1 << 24) / 256, 256>>>(x);
    snn_kernel<<<NBLK, NTHR, SM_TOTAL>>>(b1, b2, b3, b4, out);
}